// round 8
// baseline (speedup 1.0000x reference)
#include <cuda_runtime.h>
#include <cstdint>

// LIF forward scan:
//   v_t = BETA * v_{t-1} * (1 - s_{t-1}) + i_t   (hard reset)
//   s_t = (v_t >= 1.0)
// Outputs: spikes (B,T,H), membrane (B,T,H), v_final (B,H) — concatenated in d_out.
//
// R8: as R7 (float4 chains, cp.async read ring, stream-segregated flush) but
// with flush run length doubled to 16 steps (8KB/warp/stream contiguous-phase
// bursts), targeting DRAM R/W turnaround — the confirmed binding constraint.

#define LIF_BETA 0.904837f

static constexpr int Bc = 16;
static constexpr int Tc = 1024;
static constexpr int Hc = 2048;
static constexpr int CPT = 4;                 // chains per thread
static constexpr int WH  = 32 * CPT;          // 128 h per warp/block
static constexpr int CHUNK  = 16;             // time steps per stage / flush batch
static constexpr int NSTAGE = 4;              // ring depth (32KB smem)
static constexpr int NCHUNK = Tc / CHUNK;     // 64

__device__ __forceinline__ void cp_async16(uint32_t saddr, const void* gsrc) {
    asm volatile("cp.async.cg.shared.global [%0], [%1], 16;\n"
                 :: "r"(saddr), "l"(gsrc));
}
__device__ __forceinline__ void cp_commit() {
    asm volatile("cp.async.commit_group;\n");
}
template <int N>
__device__ __forceinline__ void cp_wait() {
    asm volatile("cp.async.wait_group %0;\n" :: "n"(N));
}

__global__ __launch_bounds__(32)
void lif_kernel(const float* __restrict__ in,   // (B, T, H)
                const float* __restrict__ v0,   // (B, H)
                float* __restrict__ out)        // [spikes | membrane | v_final]
{
    __shared__ float stage[NSTAGE][CHUNK][WH];  // 4*16*128*4 = 32KB

    const int lane = threadIdx.x;
    const int chain0 = blockIdx.x * WH + lane * CPT;
    const int b  = chain0 >> 11;                      // / 2048
    const int h0 = (blockIdx.x * WH) & (Hc - 1);

    const size_t plane = (size_t)Bc * Tc * Hc;
    float* __restrict__ spikes = out;
    float* __restrict__ mem    = out + plane;
    float* __restrict__ vfin   = out + 2 * plane;

    const size_t rowbase = (size_t)b * Tc * Hc + h0;
    const int elem = lane * CPT;

    // Thread `lane` copies and later consumes exactly its own 16B segment of
    // each row -> per-thread cp.async wait_group ordering suffices, no syncs.
    auto issue_stage = [&](int c) {
        const int st = c % NSTAGE;
        const size_t gbase = rowbase + (size_t)c * CHUNK * Hc + elem;
#pragma unroll
        for (int e = 0; e < CHUNK; ++e) {
            uint32_t saddr = (uint32_t)__cvta_generic_to_shared(&stage[st][e][elem]);
            cp_async16(saddr, in + gbase + (size_t)e * Hc);
        }
    };

#pragma unroll
    for (int c = 0; c < NSTAGE - 1; ++c) {
        issue_stage(c);
        cp_commit();
    }

    float4 vi = *(const float4*)(v0 + chain0);
    float va = vi.x, vb = vi.y, vc = vi.z, vd = vi.w;
    float sa = 0.f, sb = 0.f, sc = 0.f, sd = 0.f;

    float4 spb[CHUNK];   // staged spike rows (this thread's float4)
    float4 vmb[CHUNK];   // staged membrane rows

    for (int c = 0; c < NCHUNK; ++c) {
        if (c + NSTAGE - 1 < NCHUNK)
            issue_stage(c + NSTAGE - 1);
        cp_commit();
        cp_wait<NSTAGE - 1>();

        const int st = c % NSTAGE;

        // Phase 1: compute CHUNK steps, outputs staged in registers.
#pragma unroll
        for (int e = 0; e < CHUNK; ++e) {
            const float4 x = *(const float4*)&stage[st][e][elem];
            float vr;
            vr = (sa != 0.f) ? 0.f : va;  va = fmaf(LIF_BETA, vr, x.x);  sa = (va >= 1.f) ? 1.f : 0.f;
            vr = (sb != 0.f) ? 0.f : vb;  vb = fmaf(LIF_BETA, vr, x.y);  sb = (vb >= 1.f) ? 1.f : 0.f;
            vr = (sc != 0.f) ? 0.f : vc;  vc = fmaf(LIF_BETA, vr, x.z);  sc = (vc >= 1.f) ? 1.f : 0.f;
            vr = (sd != 0.f) ? 0.f : vd;  vd = fmaf(LIF_BETA, vr, x.w);  sd = (vd >= 1.f) ? 1.f : 0.f;
            spb[e] = make_float4(sa, sb, sc, sd);
            vmb[e] = make_float4(va, vb, vc, vd);
        }

        const size_t obase = rowbase + (size_t)c * CHUNK * Hc + elem;

        // Phase 2: flush spike stream as one long burst (CHUNK x 512B/warp).
#pragma unroll
        for (int e = 0; e < CHUNK; ++e)
            __stcs((float4*)(spikes + obase + (size_t)e * Hc), spb[e]);

        // Phase 3: flush membrane stream as one long burst.
#pragma unroll
        for (int e = 0; e < CHUNK; ++e)
            __stcs((float4*)(mem + obase + (size_t)e * Hc), vmb[e]);
    }

    *(float4*)(vfin + chain0) = make_float4(va, vb, vc, vd);
}

extern "C" void kernel_launch(void* const* d_in, const int* in_sizes, int n_in,
                              void* d_out, int out_size)
{
    const float* input = (const float*)d_in[0];   // (16, 1024, 2048) float32
    const float* v0    = (const float*)d_in[1];   // (16, 2048) float32
    float* out         = (float*)d_out;

    const int nchains = Bc * Hc;                  // 32768
    const int grid = nchains / WH;                // 256 blocks of 1 warp
    lif_kernel<<<grid, 32>>>(input, v0, out);
}

// round 9
// speedup vs baseline: 1.0146x; 1.0146x over previous
#include <cuda_runtime.h>
#include <cstdint>

// LIF forward scan:
//   v_t = BETA * v_{t-1} * (1 - s_{t-1}) + i_t   (hard reset)
//   s_t = (v_t >= 1.0)
// Outputs: spikes (B,T,H), membrane (B,T,H), v_final (B,H) — concatenated in d_out.
//
// R9: R7's config (float4 chains, 6-stage cp.async ring, 8-step stream-
// segregated flush) with 64-thread blocks so the two warps of a block land on
// different SMSPs (wid 0/1) instead of two single-warp blocks stacking on
// SMSP0 of the same SM — removes per-SMSP LSU issue serialization.

#define LIF_BETA 0.904837f

static constexpr int Bc = 16;
static constexpr int Tc = 1024;
static constexpr int Hc = 2048;
static constexpr int CPT = 4;                 // chains per thread
static constexpr int NT  = 64;                // threads per block (2 warps)
static constexpr int BH  = NT * CPT;          // 256 h per block
static constexpr int CHUNK  = 8;              // time steps per stage / flush batch
static constexpr int NSTAGE = 6;              // ring depth
static constexpr int NCHUNK = Tc / CHUNK;     // 128

__device__ __forceinline__ void cp_async16(uint32_t saddr, const void* gsrc) {
    asm volatile("cp.async.cg.shared.global [%0], [%1], 16;\n"
                 :: "r"(saddr), "l"(gsrc));
}
__device__ __forceinline__ void cp_commit() {
    asm volatile("cp.async.commit_group;\n");
}
template <int N>
__device__ __forceinline__ void cp_wait() {
    asm volatile("cp.async.wait_group %0;\n" :: "n"(N));
}

__global__ __launch_bounds__(NT)
void lif_kernel(const float* __restrict__ in,   // (B, T, H)
                const float* __restrict__ v0,   // (B, H)
                float* __restrict__ out)        // [spikes | membrane | v_final]
{
    __shared__ float stage[NSTAGE][CHUNK][BH];  // 6*8*256*4 = 48KB

    const int tid = threadIdx.x;
    const int chain0 = blockIdx.x * BH + tid * CPT;
    const int b  = chain0 >> 11;                      // / 2048 (blocks never straddle b)
    const int h0 = (blockIdx.x * BH) & (Hc - 1);

    const size_t plane = (size_t)Bc * Tc * Hc;
    float* __restrict__ spikes = out;
    float* __restrict__ mem    = out + plane;
    float* __restrict__ vfin   = out + 2 * plane;

    const size_t rowbase = (size_t)b * Tc * Hc + h0;
    const int elem = tid * CPT;                       // this thread's float4 slot

    // Thread copies and later consumes exactly its own 16B segment of each
    // row -> per-thread cp.async wait_group ordering suffices, no block syncs.
    auto issue_stage = [&](int c) {
        const int st = c % NSTAGE;
        const size_t gbase = rowbase + (size_t)c * CHUNK * Hc + elem;
#pragma unroll
        for (int e = 0; e < CHUNK; ++e) {
            uint32_t saddr = (uint32_t)__cvta_generic_to_shared(&stage[st][e][elem]);
            cp_async16(saddr, in + gbase + (size_t)e * Hc);
        }
    };

#pragma unroll
    for (int c = 0; c < NSTAGE - 1; ++c) {
        issue_stage(c);
        cp_commit();
    }

    float4 vi = *(const float4*)(v0 + chain0);
    float va = vi.x, vb = vi.y, vc = vi.z, vd = vi.w;
    float sa = 0.f, sb = 0.f, sc = 0.f, sd = 0.f;

    float4 spb[CHUNK];   // staged spike rows (this thread's float4)
    float4 vmb[CHUNK];   // staged membrane rows

    for (int c = 0; c < NCHUNK; ++c) {
        if (c + NSTAGE - 1 < NCHUNK)
            issue_stage(c + NSTAGE - 1);
        cp_commit();
        cp_wait<NSTAGE - 1>();

        const int st = c % NSTAGE;

        // Phase 1: compute CHUNK steps, outputs staged in registers.
#pragma unroll
        for (int e = 0; e < CHUNK; ++e) {
            const float4 x = *(const float4*)&stage[st][e][elem];
            float vr;
            vr = (sa != 0.f) ? 0.f : va;  va = fmaf(LIF_BETA, vr, x.x);  sa = (va >= 1.f) ? 1.f : 0.f;
            vr = (sb != 0.f) ? 0.f : vb;  vb = fmaf(LIF_BETA, vr, x.y);  sb = (vb >= 1.f) ? 1.f : 0.f;
            vr = (sc != 0.f) ? 0.f : vc;  vc = fmaf(LIF_BETA, vr, x.z);  sc = (vc >= 1.f) ? 1.f : 0.f;
            vr = (sd != 0.f) ? 0.f : vd;  vd = fmaf(LIF_BETA, vr, x.w);  sd = (vd >= 1.f) ? 1.f : 0.f;
            spb[e] = make_float4(sa, sb, sc, sd);
            vmb[e] = make_float4(va, vb, vc, vd);
        }

        const size_t obase = rowbase + (size_t)c * CHUNK * Hc + elem;

        // Phase 2: flush spike stream as one burst (CHUNK x 1KB/block).
#pragma unroll
        for (int e = 0; e < CHUNK; ++e)
            __stcs((float4*)(spikes + obase + (size_t)e * Hc), spb[e]);

        // Phase 3: flush membrane stream as one burst.
#pragma unroll
        for (int e = 0; e < CHUNK; ++e)
            __stcs((float4*)(mem + obase + (size_t)e * Hc), vmb[e]);
    }

    *(float4*)(vfin + chain0) = make_float4(va, vb, vc, vd);
}

extern "C" void kernel_launch(void* const* d_in, const int* in_sizes, int n_in,
                              void* d_out, int out_size)
{
    const float* input = (const float*)d_in[0];   // (16, 1024, 2048) float32
    const float* v0    = (const float*)d_in[1];   // (16, 2048) float32
    float* out         = (float*)d_out;

    const int nchains = Bc * Hc;                  // 32768
    const int grid = nchains / BH;                // 128 blocks of 2 warps
    lif_kernel<<<grid, NT>>>(input, v0, out);
}